// round 15
// baseline (speedup 1.0000x reference)
#include <cuda_runtime.h>
#include <cuda_fp16.h>
#include <math_constants.h>
#include <cstdint>

#define B_ 4
#define T_ 2048
#define C_ 1024
#define H_ 16
#define D_ 64
#define S_ (B_*T_)   // 8192

// Scratch (device globals) — all fp16 payloads stored as packed half2 words.
__device__ uint32_t g_x16 [S_*C_/2];        // x as fp16
__device__ uint32_t g_wat16[3*C_*C_/2];     // w_attn TRANSPOSED [N][K] fp16
__device__ uint32_t g_wpt16[C_*C_/2];       // w_proj TRANSPOSED [N][K] fp16
__device__ uint32_t g_y16 [S_*C_/2];        // attention output fp16
__device__ uint32_t g_q16 [B_*H_*T_*D_/2];  // q * (1/8)*log2e, [B,H,T,D]
__device__ uint32_t g_k16 [B_*H_*T_*D_/2];  // [B,H,T,D]
__device__ uint32_t g_vn16[B_*H_*T_*D_/2];  // v natural
__device__ uint32_t g_vt16[B_*H_*D_*T_/2];  // v transposed [B,H,D,T]

// pack two floats -> half2 word {lo, hi}
__device__ __forceinline__ uint32_t f2h2(float lo, float hi) {
    uint32_t r;
    asm("cvt.rn.f16x2.f32 %0, %1, %2;" : "=r"(r) : "f"(hi), "f"(lo));
    return r;
}
__device__ __forceinline__ float ex2f(float x) {
    float r;
    asm("ex2.approx.f32 %0, %1;" : "=f"(r) : "f"(x));
    return r;
}

// mma.sync m16n8k16 fp16 in / fp32 acc.
__device__ __forceinline__ void mma_f16(float c[4],
                                        uint32_t a0, uint32_t a1, uint32_t a2, uint32_t a3,
                                        uint32_t b0, uint32_t b1) {
    asm volatile(
        "mma.sync.aligned.m16n8k16.row.col.f32.f16.f16.f32 "
        "{%0,%1,%2,%3}, {%4,%5,%6,%7}, {%8,%9}, {%0,%1,%2,%3};"
        : "+f"(c[0]), "+f"(c[1]), "+f"(c[2]), "+f"(c[3])
        : "r"(a0), "r"(a1), "r"(a2), "r"(a3), "r"(b0), "r"(b1));
}

// ldmatrix x4 b16
__device__ __forceinline__ void ldsm4(uint32_t& r0, uint32_t& r1,
                                      uint32_t& r2, uint32_t& r3, uint32_t a) {
    asm volatile("ldmatrix.sync.aligned.m8n8.x4.shared.b16 {%0,%1,%2,%3}, [%4];"
                 : "=r"(r0), "=r"(r1), "=r"(r2), "=r"(r3) : "r"(a));
}

// ---------------------------------------------------------------------------
// fp32 -> fp16 bulk converter (for x)
// ---------------------------------------------------------------------------
__global__ __launch_bounds__(256)
void conv_f16(const float* __restrict__ s, uint32_t* __restrict__ d, int n4)
{
    const int i = blockIdx.x * blockDim.x + threadIdx.x;
    if (i < n4) {
        float4 v = ((const float4*)s)[i];
        ((uint2*)d)[i] = make_uint2(f2h2(v.x, v.y), f2h2(v.z, v.w));
    }
}

// ---------------------------------------------------------------------------
// fp32 [K][N] -> fp16 transposed [N][K]. Tiles of 64 k x 32 n.
// ---------------------------------------------------------------------------
__global__ __launch_bounds__(256)
void convT_f16(const float* __restrict__ w, uint32_t* __restrict__ wt,
               int Kd, int Nd)
{
    __shared__ float t[64][33];
    const int n0 = blockIdx.x * 32, k0 = blockIdx.y * 64;
    const int tid = threadIdx.x;
    #pragma unroll
    for (int i = 0; i < 8; ++i) {
        const int idx = tid + i * 256;
        const int r = idx >> 5, c = idx & 31;
        t[r][c] = w[(size_t)(k0 + r) * Nd + n0 + c];
    }
    __syncthreads();
    #pragma unroll
    for (int i = 0; i < 4; ++i) {
        const int idx = tid + i * 256;
        const int n = idx >> 5, k2 = idx & 31;
        wt[(size_t)(n0 + n) * (Kd / 2) + k0 / 2 + k2] =
            f2h2(t[2 * k2][n], t[2 * k2 + 1][n]);
    }
}

// ---------------------------------------------------------------------------
// v natural [B,H,T,D] fp16 -> transposed [B,H,D,T] fp16. 64x64-element tiles.
// ---------------------------------------------------------------------------
__global__ __launch_bounds__(256)
void vtrans()
{
    __shared__ uint16_t ts[64][66];
    const int bh = blockIdx.y;
    const int t0 = blockIdx.x * 64;
    const int tid = threadIdx.x;
    const uint32_t* in = g_vn16 + ((size_t)bh * T_ + t0) * 32;
    #pragma unroll
    for (int i = 0; i < 8; ++i) {
        const int idx = tid + i * 256;
        const int r = idx >> 5, c2 = idx & 31;
        const uint32_t u = in[r * 32 + c2];
        ts[2 * c2][r]     = (uint16_t)(u & 0xffffu);
        ts[2 * c2 + 1][r] = (uint16_t)(u >> 16);
    }
    __syncthreads();
    uint32_t* outp = g_vt16 + (size_t)bh * 64 * (T_ / 2);
    #pragma unroll
    for (int i = 0; i < 8; ++i) {
        const int idx = tid + i * 256;
        const int d = idx >> 5, t2 = idx & 31;
        const uint32_t lo = ts[d][2 * t2], hi = ts[d][2 * t2 + 1];
        outp[(size_t)d * (T_ / 2) + t0 / 2 + t2] = lo | (hi << 16);
    }
}

// ---------------------------------------------------------------------------
// FP16 tensor-core GEMM: 128x128 CTA, 256 thr, 2 CTAs/SM, cp.async 3-stage,
// K-chunks of 64. ISSUE hoisted before COMPUTE (extra latency cover).
// ---------------------------------------------------------------------------
#define PAW 36
#define AW (128*PAW)         // 4608 words per tile
#define STW (2*AW)           // 9216 words per stage
#define GEMM_SMEM (3*STW*4)  // 110592 B

template<int MODE>
__global__ __launch_bounds__(256, 2)
void gemm_mma(const uint32_t* __restrict__ A2,    // [M][K/2] half2 words
              const uint32_t* __restrict__ Wt2,   // [N][K/2]
              const float* __restrict__ bias,
              float* __restrict__ out,
              int N, int K)
{
    extern __shared__ uint32_t sm4[];
    uint32_t sbase;
    asm("{ .reg .u64 t; cvta.to.shared.u64 t, %1; cvt.u32.u64 %0, t; }"
        : "=r"(sbase) : "l"(sm4));

    const int tid = threadIdx.x;
    const int wid = tid >> 5, lane = tid & 31;
    const int g = lane >> 2, tig = lane & 3;
    const int rowin = lane & 7, mA = lane >> 3;
    const int wm = (wid & 1) * 64;
    const int wn = (wid >> 1) * 32;
    const int bm = blockIdx.y * 128, bn = blockIdx.x * 128;
    const int K2 = K / 2;

    const uint32_t aBase = sbase + (uint32_t)(((wm + rowin + ((mA & 1) ? 8 : 0)) * PAW
                                              + ((mA & 2) ? 4 : 0)) * 4);
    const uint32_t bBase = sbase + (uint32_t)((AW + (wn + rowin + ((mA & 1) ? 8 : 0)) * PAW
                                              + ((mA & 2) ? 4 : 0)) * 4);

    float acc[4][4][4];
    #pragma unroll
    for (int i = 0; i < 4; ++i)
        #pragma unroll
        for (int j = 0; j < 4; ++j)
            #pragma unroll
            for (int k = 0; k < 4; ++k) acc[i][j][k] = 0.f;

    const int nch = K / 64;

    auto ISSUE = [&](int c, int st) {
        const int k0w = c * 32;
        const uint32_t so = st * STW;
        #pragma unroll
        for (int i = 0; i < 4; ++i) {
            const int idx = tid + i * 256;
            const int row = idx >> 3, kq = idx & 7;
            const uint32_t* src = A2 + (size_t)(bm + row) * K2 + k0w + kq * 4;
            const uint32_t dst = sbase + (so + row * PAW + kq * 4) * 4;
            asm volatile("cp.async.cg.shared.global [%0], [%1], 16;"
                         :: "r"(dst), "l"(src) : "memory");
        }
        #pragma unroll
        for (int i = 0; i < 4; ++i) {
            const int idx = tid + i * 256;
            const int row = idx >> 3, kq = idx & 7;
            const uint32_t* src = Wt2 + (size_t)(bn + row) * K2 + k0w + kq * 4;
            const uint32_t dst = sbase + (so + AW + row * PAW + kq * 4) * 4;
            asm volatile("cp.async.cg.shared.global [%0], [%1], 16;"
                         :: "r"(dst), "l"(src) : "memory");
        }
        asm volatile("cp.async.commit_group;" ::: "memory");
    };

    auto COMPUTE = [&](int st) {
        const uint32_t so4 = (uint32_t)(st * STW * 4);
        #pragma unroll
        for (int ks = 0; ks < 4; ++ks) {
            uint32_t af[4][4];
            #pragma unroll
            for (int mf = 0; mf < 4; ++mf)
                ldsm4(af[mf][0], af[mf][1], af[mf][2], af[mf][3],
                      aBase + so4 + (uint32_t)((mf * 16 * PAW + ks * 8) * 4));
            uint32_t bf[4][2];
            #pragma unroll
            for (int j = 0; j < 2; ++j)
                ldsm4(bf[2*j][0], bf[2*j+1][0], bf[2*j][1], bf[2*j+1][1],
                      bBase + so4 + (uint32_t)((j * 16 * PAW + ks * 8) * 4));
            #pragma unroll
            for (int mf = 0; mf < 4; ++mf)
                #pragma unroll
                for (int nf = 0; nf < 4; ++nf)
                    mma_f16(acc[mf][nf], af[mf][0], af[mf][1], af[mf][2], af[mf][3],
                            bf[nf][0], bf[nf][1]);
        }
    };

    ISSUE(0, 0);
    ISSUE(1, 1);
    for (int c = 0; c < nch; ++c) {
        if (c + 1 < nch) asm volatile("cp.async.wait_group 1;" ::: "memory");
        else             asm volatile("cp.async.wait_group 0;" ::: "memory");
        __syncthreads();
        if (c + 2 < nch) ISSUE(c + 2, (c + 2) % 3);   // hoisted: 2 COMPUTE spans of cover
        COMPUTE(c % 3);
    }

    #pragma unroll
    for (int mf = 0; mf < 4; ++mf) {
        const int r0 = bm + wm + mf * 16 + g;
        #pragma unroll
        for (int nf = 0; nf < 4; ++nf) {
            const int n0 = bn + wn + nf * 8 + tig * 2;
            const float bv0 = bias[n0], bv1 = bias[n0 + 1];
            float v00 = acc[mf][nf][0] + bv0, v01 = acc[mf][nf][1] + bv1;
            float v10 = acc[mf][nf][2] + bv0, v11 = acc[mf][nf][3] + bv1;
            if (MODE == 0) {
                const int part = n0 >> 10;
                const int cl = n0 & 1023;
                const int hh = cl >> 6, dd = cl & 63;
                const int bb0 = r0 >> 11, tt0 = r0 & 2047;
                const int r1 = r0 + 8;
                const int bb1 = r1 >> 11, tt1 = r1 & 2047;
                const int w0 = (((bb0 * H_ + hh) * T_ + tt0) << 5) + (dd >> 1);
                const int w1 = (((bb1 * H_ + hh) * T_ + tt1) << 5) + (dd >> 1);
                uint32_t* dst;
                if (part == 0) {
                    dst = g_q16;
                    const float qs = 0.125f * 1.4426950408889634f;
                    v00 *= qs; v01 *= qs; v10 *= qs; v11 *= qs;
                } else dst = (part == 1) ? g_k16 : g_vn16;
                dst[w0] = f2h2(v00, v01);
                dst[w1] = f2h2(v10, v11);
            } else {
                *(float2*)&out[(size_t)r0 * N + n0]       = make_float2(v00, v01);
                *(float2*)&out[(size_t)(r0 + 8) * N + n0] = make_float2(v10, v11);
            }
        }
    }
}

// ---------------------------------------------------------------------------
// FP16 tensor-core causal flash attention. Double key-tiles: 128 keys per
// cp.async buffer, computed as two 64-key sub-passes between one barrier
// pair (halves barriers/waits). No running max; per-warp masked-sub skip.
// K plane: 128 rows x 36 words. VT plane: 64 d-rows x 68 words (128 keys).
// P: 128 rows x 36 words, reused per sub (protected by __syncwarp).
// smem total 90112 B -> 2 CTAs/SM.
// ---------------------------------------------------------------------------
#define BQ 128
#define PW36 36
#define PW68 68
#define KPW (128*PW36)          // 4608 words (K plane, 128 keys)
#define VPW (64*PW68)           // 4352 words (VT plane, 128 keys)
#define BUFW (KPW+VPW)          // 8960 words per buffer
#define PS_OFF (2*BUFW)         // 17920
#define ATTN_SMEM_BYTES ((PS_OFF + BQ*PW36)*4)   // 90112 B

__global__ __launch_bounds__(256, 2)
void attn_mma()
{
    extern __shared__ uint32_t sw[];
    uint32_t sbase;
    asm("{ .reg .u64 t; cvta.to.shared.u64 t, %1; cvt.u32.u64 %0, t; }"
        : "=r"(sbase) : "l"(sw));

    const int tid = threadIdx.x, wid = tid >> 5, lane = tid & 31;
    const int g = lane >> 2, tig = lane & 3;
    const int rowin = lane & 7, mA = lane >> 3;
    const int qt = gridDim.x - 1 - blockIdx.x;   // big tiles first
    const int h = blockIdx.y, b = blockIdx.z;
    const int qbase = qt * BQ;
    const size_t pb2  = (size_t)((b * H_ + h) * T_) * 32;        // q/k word base
    const size_t vtb2 = (size_t)((b * H_ + h) * D_) * (T_ / 2);  // vt word base

    const uint32_t kOff = (uint32_t)(((rowin + ((mA & 1) ? 8 : 0)) * PW36
                                     + ((mA & 2) ? 4 : 0)) * 4);
    const uint32_t vOff = (uint32_t)(((rowin + ((mA & 1) ? 8 : 0)) * PW68
                                     + ((mA & 2) ? 4 : 0)) * 4);
    const uint32_t pBase = sbase + (uint32_t)(PS_OFF * 4)
        + (uint32_t)(((wid * 16 + rowin + ((mA & 1) ? 8 : 0)) * PW36
                     + ((mA & 2) ? 4 : 0)) * 4);

    // Q fragments (4 k16 steps), register-resident
    uint32_t aq[4][4];
    {
        const uint32_t* q2 = g_q16 + pb2;
        const int r0 = qbase + wid * 16 + g;
        #pragma unroll
        for (int ks = 0; ks < 4; ++ks) {
            aq[ks][0] = q2[(size_t)r0 * 32 + ks * 8 + tig];
            aq[ks][1] = q2[(size_t)(r0 + 8) * 32 + ks * 8 + tig];
            aq[ks][2] = q2[(size_t)r0 * 32 + ks * 8 + tig + 4];
            aq[ks][3] = q2[(size_t)(r0 + 8) * 32 + ks * 8 + tig + 4];
        }
    }

    float oacc[8][4];
    #pragma unroll
    for (int nf = 0; nf < 8; ++nf)
        #pragma unroll
        for (int j = 0; j < 4; ++j) oacc[nf][j] = 0.f;
    float l0 = 0.f, l1 = 0.f;

    const int nkt2 = qt + 1;                      // 128-key double tiles
    const int wmaxrow = qbase + wid * 16 + 15;

    auto ISSUE = [&](int kt2, int buf) {
        const uint32_t bufo = buf * BUFW;
        #pragma unroll
        for (int i = 0; i < 4; ++i) {           // K plane: 128 rows x 8 16B
            const int idx = tid + i * 256;
            const int row = idx >> 3, c16 = idx & 7;
            const uint32_t* src = g_k16 + pb2 + (size_t)(kt2 * 128 + row) * 32 + c16 * 4;
            const uint32_t dst = sbase + (bufo + row * PW36 + c16 * 4) * 4;
            asm volatile("cp.async.cg.shared.global [%0], [%1], 16;"
                         :: "r"(dst), "l"(src) : "memory");
        }
        #pragma unroll
        for (int i = 0; i < 4; ++i) {           // VT plane: 64 d-rows x 16 16B
            const int idx = tid + i * 256;
            const int row = idx >> 4, c16 = idx & 15;
            const uint32_t* src = g_vt16 + vtb2 + (size_t)row * (T_ / 2)
                                  + kt2 * 64 + c16 * 4;
            const uint32_t dst = sbase + (bufo + KPW + row * PW68 + c16 * 4) * 4;
            asm volatile("cp.async.cg.shared.global [%0], [%1], 16;"
                         :: "r"(dst), "l"(src) : "memory");
        }
        asm volatile("cp.async.commit_group;" ::: "memory");
    };

    ISSUE(0, 0);
    if (nkt2 > 1) ISSUE(1, 1);

    for (int kt2 = 0; kt2 < nkt2; ++kt2) {
        if (kt2 < nkt2 - 1) asm volatile("cp.async.wait_group 1;" ::: "memory");
        else                asm volatile("cp.async.wait_group 0;" ::: "memory");
        __syncthreads();

        const uint32_t bufb = sbase + (uint32_t)(((kt2 & 1) * BUFW) * 4);
        uint32_t* Ps = sw + PS_OFF;

        #pragma unroll
        for (int sub = 0; sub < 2; ++sub) {
            const int ktb = kt2 * 128 + sub * 64;
            if (ktb > wmaxrow) break;           // warp-uniform masked-sub skip

            const uint32_t kAddr = bufb + (uint32_t)((sub * 64 * PW36) * 4) + kOff;
            const uint32_t vAddr = bufb + (uint32_t)((KPW + sub * 32) * 4) + vOff;

            // ---- S = Q K^T (log2 domain) ----
            float sa[8][4];
            #pragma unroll
            for (int nf = 0; nf < 8; ++nf)
                #pragma unroll
                for (int j = 0; j < 4; ++j) sa[nf][j] = 0.f;
            #pragma unroll
            for (int ks = 0; ks < 4; ++ks) {
                #pragma unroll
                for (int j = 0; j < 4; ++j) {
                    uint32_t b0, b1, b2, b3;
                    ldsm4(b0, b1, b2, b3,
                          kAddr + (uint32_t)((j * 16 * PW36 + ks * 8) * 4));
                    mma_f16(sa[2*j],   aq[ks][0], aq[ks][1], aq[ks][2], aq[ks][3], b0, b2);
                    mma_f16(sa[2*j+1], aq[ks][0], aq[ks][1], aq[ks][2], aq[ks][3], b1, b3);
                }
            }

            // ---- causal mask ----
            const int rg0 = qbase + wid * 16 + g, rg1 = rg0 + 8;
            if (ktb + 63 > rg0) {
                #pragma unroll
                for (int nf = 0; nf < 8; ++nf) {
                    const int c0 = ktb + nf * 8 + 2 * tig;
                    if (c0     > rg0) sa[nf][0] = -CUDART_INF_F;
                    if (c0 + 1 > rg0) sa[nf][1] = -CUDART_INF_F;
                    if (c0     > rg1) sa[nf][2] = -CUDART_INF_F;
                    if (c0 + 1 > rg1) sa[nf][3] = -CUDART_INF_F;
                }
            }

            // ---- p = ex2(s); store P (fp16) ----
            float ls0 = 0.f, ls1 = 0.f;
            const int prow = wid * 16 + g;
            #pragma unroll
            for (int nf = 0; nf < 8; ++nf) {
                const float p0 = ex2f(sa[nf][0]), p1 = ex2f(sa[nf][1]);
                const float p2 = ex2f(sa[nf][2]), p3 = ex2f(sa[nf][3]);
                ls0 += p0 + p1; ls1 += p2 + p3;
                Ps[prow * PW36 + nf * 4 + tig]       = f2h2(p0, p1);
                Ps[(prow + 8) * PW36 + nf * 4 + tig] = f2h2(p2, p3);
            }
            l0 += ls0;
            l1 += ls1;
            __syncwarp();   // P rows warp-private: stores -> ldsm ordering

            // ---- O += P V ----
            #pragma unroll
            for (int ks = 0; ks < 4; ++ks) {
                uint32_t p0, p1, p2, p3;
                ldsm4(p0, p1, p2, p3, pBase + (uint32_t)((ks * 8) * 4));
                #pragma unroll
                for (int j = 0; j < 4; ++j) {
                    uint32_t v0, v1, v2, v3;
                    ldsm4(v0, v1, v2, v3,
                          vAddr + (uint32_t)((j * 16 * PW68 + ks * 8) * 4));
                    mma_f16(oacc[2*j],   p0, p1, p2, p3, v0, v2);
                    mma_f16(oacc[2*j+1], p0, p1, p2, p3, v1, v3);
                }
            }
            __syncwarp();   // PV ldsm done before next sub overwrites P
        }

        __syncthreads();
        if (kt2 + 2 < nkt2) ISSUE(kt2 + 2, kt2 & 1);
    }

    // ---- row-sum quad reduce + finalize (y fp16 for proj GEMM) ----
    l0 += __shfl_xor_sync(0xffffffffu, l0, 1);
    l0 += __shfl_xor_sync(0xffffffffu, l0, 2);
    l1 += __shfl_xor_sync(0xffffffffu, l1, 1);
    l1 += __shfl_xor_sync(0xffffffffu, l1, 2);
    const float i0 = __frcp_rn(l0), i1 = __frcp_rn(l1);
    const int rg0 = qbase + wid * 16 + g;
    uint32_t* y0 = g_y16 + ((size_t)(b * T_ + rg0) * C_ + h * D_) / 2;
    uint32_t* y1 = g_y16 + ((size_t)(b * T_ + rg0 + 8) * C_ + h * D_) / 2;
    #pragma unroll
    for (int nf = 0; nf < 8; ++nf) {
        y0[nf * 4 + tig] = f2h2(oacc[nf][0] * i0, oacc[nf][1] * i0);
        y1[nf * 4 + tig] = f2h2(oacc[nf][2] * i1, oacc[nf][3] * i1);
    }
}

// ---------------------------------------------------------------------------
extern "C" void kernel_launch(void* const* d_in, const int* in_sizes, int n_in,
                              void* d_out, int out_size)
{
    const float* x      = (const float*)d_in[0];
    const float* w_attn = (const float*)d_in[1];
    const float* b_attn = (const float*)d_in[2];
    const float* w_proj = (const float*)d_in[3];
    const float* b_proj = (const float*)d_in[4];
    float* out = (float*)d_out;

    cudaFuncSetAttribute(gemm_mma<0>, cudaFuncAttributeMaxDynamicSharedMemorySize, GEMM_SMEM);
    cudaFuncSetAttribute(gemm_mma<1>, cudaFuncAttributeMaxDynamicSharedMemorySize, GEMM_SMEM);
    cudaFuncSetAttribute(attn_mma, cudaFuncAttributeMaxDynamicSharedMemorySize, ATTN_SMEM_BYTES);

    uint32_t* px;  cudaGetSymbolAddress((void**)&px,  g_x16);
    uint32_t* pat; cudaGetSymbolAddress((void**)&pat, g_wat16);
    uint32_t* ppt; cudaGetSymbolAddress((void**)&ppt, g_wpt16);
    uint32_t* py;  cudaGetSymbolAddress((void**)&py,  g_y16);

    // 0) convert x to fp16; convert+transpose weights to [N][K] fp16
    conv_f16<<<(S_*C_/4 + 255)/256, 256>>>(x, px, S_*C_/4);
    convT_f16<<<dim3(3*C_/32, C_/64), 256>>>(w_attn, pat, C_, 3*C_);
    convT_f16<<<dim3(C_/32,   C_/64), 256>>>(w_proj, ppt, C_, C_);

    // 1) QKV GEMM (fp16 m16n8k16) -> q/k/vn fp16 planes
    gemm_mma<0><<<dim3(3*C_/128, S_/128), 256, GEMM_SMEM>>>(px, pat, b_attn, nullptr, 3*C_, C_);

    // 1b) transpose v -> [B,H,D,T] fp16
    vtrans<<<dim3(T_/64, B_*H_), 256>>>();

    // 2) FP16 tensor-core causal flash attention -> g_y16
    attn_mma<<<dim3(T_/BQ, H_, B_), 256, ATTN_SMEM_BYTES>>>();

    // 3) Proj GEMM (fp16) + bias -> fp32 out
    gemm_mma<1><<<dim3(C_/128, S_/128), 256, GEMM_SMEM>>>(py, ppt, b_proj, out, C_, C_);
}

// round 16
// speedup vs baseline: 1.0566x; 1.0566x over previous
#include <cuda_runtime.h>
#include <cuda_fp16.h>
#include <math_constants.h>
#include <cstdint>

#define B_ 4
#define T_ 2048
#define C_ 1024
#define H_ 16
#define D_ 64
#define S_ (B_*T_)   // 8192

// Scratch (device globals) — all fp16 payloads stored as packed half2 words.
__device__ uint32_t g_x16 [S_*C_/2];        // x as fp16
__device__ uint32_t g_wat16[3*C_*C_/2];     // w_attn TRANSPOSED [N][K] fp16
__device__ uint32_t g_wpt16[C_*C_/2];       // w_proj TRANSPOSED [N][K] fp16
__device__ uint32_t g_y16 [S_*C_/2];        // attention output fp16
__device__ uint32_t g_q16 [B_*H_*T_*D_/2];  // q * (1/8)*log2e, [B,H,T,D]
__device__ uint32_t g_k16 [B_*H_*T_*D_/2];  // [B,H,T,D]
__device__ uint32_t g_v16 [B_*H_*T_*D_/2];  // v natural [B,H,T,D]

// pack two floats -> half2 word {lo, hi}
__device__ __forceinline__ uint32_t f2h2(float lo, float hi) {
    uint32_t r;
    asm("cvt.rn.f16x2.f32 %0, %1, %2;" : "=r"(r) : "f"(hi), "f"(lo));
    return r;
}
__device__ __forceinline__ float ex2f(float x) {
    float r;
    asm("ex2.approx.f32 %0, %1;" : "=f"(r) : "f"(x));
    return r;
}

// mma.sync m16n8k16 fp16 in / fp32 acc.
__device__ __forceinline__ void mma_f16(float c[4],
                                        uint32_t a0, uint32_t a1, uint32_t a2, uint32_t a3,
                                        uint32_t b0, uint32_t b1) {
    asm volatile(
        "mma.sync.aligned.m16n8k16.row.col.f32.f16.f16.f32 "
        "{%0,%1,%2,%3}, {%4,%5,%6,%7}, {%8,%9}, {%0,%1,%2,%3};"
        : "+f"(c[0]), "+f"(c[1]), "+f"(c[2]), "+f"(c[3])
        : "r"(a0), "r"(a1), "r"(a2), "r"(a3), "r"(b0), "r"(b1));
}

// ldmatrix x4 b16 (non-transposed)
__device__ __forceinline__ void ldsm4(uint32_t& r0, uint32_t& r1,
                                      uint32_t& r2, uint32_t& r3, uint32_t a) {
    asm volatile("ldmatrix.sync.aligned.m8n8.x4.shared.b16 {%0,%1,%2,%3}, [%4];"
                 : "=r"(r0), "=r"(r1), "=r"(r2), "=r"(r3) : "r"(a));
}
// ldmatrix x4 b16 TRANSPOSED: lane l of tile m gets {M[2tig][g], M[2tig+1][g]}
// == B-fragment of M^T built from natural (row-major) M.
__device__ __forceinline__ void ldsm4t(uint32_t& r0, uint32_t& r1,
                                       uint32_t& r2, uint32_t& r3, uint32_t a) {
    asm volatile("ldmatrix.sync.aligned.m8n8.x4.trans.shared.b16 {%0,%1,%2,%3}, [%4];"
                 : "=r"(r0), "=r"(r1), "=r"(r2), "=r"(r3) : "r"(a));
}

// ---------------------------------------------------------------------------
// fp32 -> fp16 bulk converter (for x)
// ---------------------------------------------------------------------------
__global__ __launch_bounds__(256)
void conv_f16(const float* __restrict__ s, uint32_t* __restrict__ d, int n4)
{
    const int i = blockIdx.x * blockDim.x + threadIdx.x;
    if (i < n4) {
        float4 v = ((const float4*)s)[i];
        ((uint2*)d)[i] = make_uint2(f2h2(v.x, v.y), f2h2(v.z, v.w));
    }
}

// ---------------------------------------------------------------------------
// fp32 [K][N] -> fp16 transposed [N][K]. Tiles of 64 k x 32 n.
// ---------------------------------------------------------------------------
__global__ __launch_bounds__(256)
void convT_f16(const float* __restrict__ w, uint32_t* __restrict__ wt,
               int Kd, int Nd)
{
    __shared__ float t[64][33];
    const int n0 = blockIdx.x * 32, k0 = blockIdx.y * 64;
    const int tid = threadIdx.x;
    #pragma unroll
    for (int i = 0; i < 8; ++i) {
        const int idx = tid + i * 256;
        const int r = idx >> 5, c = idx & 31;
        t[r][c] = w[(size_t)(k0 + r) * Nd + n0 + c];
    }
    __syncthreads();
    #pragma unroll
    for (int i = 0; i < 4; ++i) {
        const int idx = tid + i * 256;
        const int n = idx >> 5, k2 = idx & 31;
        wt[(size_t)(n0 + n) * (Kd / 2) + k0 / 2 + k2] =
            f2h2(t[2 * k2][n], t[2 * k2 + 1][n]);
    }
}

// ---------------------------------------------------------------------------
// FP16 tensor-core GEMM: 128x128 CTA, 256 thr, 2 CTAs/SM, cp.async 3-stage,
// K-chunks of 64 (R14 loop order: COMPUTE then ISSUE).
// ---------------------------------------------------------------------------
#define PAW 36
#define AW (128*PAW)         // 4608 words per tile
#define STW (2*AW)           // 9216 words per stage
#define GEMM_SMEM (3*STW*4)  // 110592 B

template<int MODE>
__global__ __launch_bounds__(256, 2)
void gemm_mma(const uint32_t* __restrict__ A2,    // [M][K/2] half2 words
              const uint32_t* __restrict__ Wt2,   // [N][K/2]
              const float* __restrict__ bias,
              float* __restrict__ out,
              int N, int K)
{
    extern __shared__ uint32_t sm4[];
    uint32_t sbase;
    asm("{ .reg .u64 t; cvta.to.shared.u64 t, %1; cvt.u32.u64 %0, t; }"
        : "=r"(sbase) : "l"(sm4));

    const int tid = threadIdx.x;
    const int wid = tid >> 5, lane = tid & 31;
    const int g = lane >> 2, tig = lane & 3;
    const int rowin = lane & 7, mA = lane >> 3;
    const int wm = (wid & 1) * 64;
    const int wn = (wid >> 1) * 32;
    const int bm = blockIdx.y * 128, bn = blockIdx.x * 128;
    const int K2 = K / 2;

    const uint32_t aBase = sbase + (uint32_t)(((wm + rowin + ((mA & 1) ? 8 : 0)) * PAW
                                              + ((mA & 2) ? 4 : 0)) * 4);
    const uint32_t bBase = sbase + (uint32_t)((AW + (wn + rowin + ((mA & 1) ? 8 : 0)) * PAW
                                              + ((mA & 2) ? 4 : 0)) * 4);

    float acc[4][4][4];
    #pragma unroll
    for (int i = 0; i < 4; ++i)
        #pragma unroll
        for (int j = 0; j < 4; ++j)
            #pragma unroll
            for (int k = 0; k < 4; ++k) acc[i][j][k] = 0.f;

    const int nch = K / 64;

    auto ISSUE = [&](int c, int st) {
        const int k0w = c * 32;
        const uint32_t so = st * STW;
        #pragma unroll
        for (int i = 0; i < 4; ++i) {
            const int idx = tid + i * 256;
            const int row = idx >> 3, kq = idx & 7;
            const uint32_t* src = A2 + (size_t)(bm + row) * K2 + k0w + kq * 4;
            const uint32_t dst = sbase + (so + row * PAW + kq * 4) * 4;
            asm volatile("cp.async.cg.shared.global [%0], [%1], 16;"
                         :: "r"(dst), "l"(src) : "memory");
        }
        #pragma unroll
        for (int i = 0; i < 4; ++i) {
            const int idx = tid + i * 256;
            const int row = idx >> 3, kq = idx & 7;
            const uint32_t* src = Wt2 + (size_t)(bn + row) * K2 + k0w + kq * 4;
            const uint32_t dst = sbase + (so + AW + row * PAW + kq * 4) * 4;
            asm volatile("cp.async.cg.shared.global [%0], [%1], 16;"
                         :: "r"(dst), "l"(src) : "memory");
        }
        asm volatile("cp.async.commit_group;" ::: "memory");
    };

    auto COMPUTE = [&](int st) {
        const uint32_t so4 = (uint32_t)(st * STW * 4);
        #pragma unroll
        for (int ks = 0; ks < 4; ++ks) {
            uint32_t af[4][4];
            #pragma unroll
            for (int mf = 0; mf < 4; ++mf)
                ldsm4(af[mf][0], af[mf][1], af[mf][2], af[mf][3],
                      aBase + so4 + (uint32_t)((mf * 16 * PAW + ks * 8) * 4));
            uint32_t bf[4][2];
            #pragma unroll
            for (int j = 0; j < 2; ++j)
                ldsm4(bf[2*j][0], bf[2*j+1][0], bf[2*j][1], bf[2*j+1][1],
                      bBase + so4 + (uint32_t)((j * 16 * PAW + ks * 8) * 4));
            #pragma unroll
            for (int mf = 0; mf < 4; ++mf)
                #pragma unroll
                for (int nf = 0; nf < 4; ++nf)
                    mma_f16(acc[mf][nf], af[mf][0], af[mf][1], af[mf][2], af[mf][3],
                            bf[nf][0], bf[nf][1]);
        }
    };

    ISSUE(0, 0);
    ISSUE(1, 1);
    for (int c = 0; c < nch; ++c) {
        if (c + 1 < nch) asm volatile("cp.async.wait_group 1;" ::: "memory");
        else             asm volatile("cp.async.wait_group 0;" ::: "memory");
        __syncthreads();
        COMPUTE(c % 3);
        if (c + 2 < nch) ISSUE(c + 2, (c + 2) % 3);
    }

    #pragma unroll
    for (int mf = 0; mf < 4; ++mf) {
        const int r0 = bm + wm + mf * 16 + g;
        #pragma unroll
        for (int nf = 0; nf < 4; ++nf) {
            const int n0 = bn + wn + nf * 8 + tig * 2;
            const float bv0 = bias[n0], bv1 = bias[n0 + 1];
            float v00 = acc[mf][nf][0] + bv0, v01 = acc[mf][nf][1] + bv1;
            float v10 = acc[mf][nf][2] + bv0, v11 = acc[mf][nf][3] + bv1;
            if (MODE == 0) {
                const int part = n0 >> 10;
                const int cl = n0 & 1023;
                const int hh = cl >> 6, dd = cl & 63;
                const int bb0 = r0 >> 11, tt0 = r0 & 2047;
                const int r1 = r0 + 8;
                const int bb1 = r1 >> 11, tt1 = r1 & 2047;
                const int w0 = (((bb0 * H_ + hh) * T_ + tt0) << 5) + (dd >> 1);
                const int w1 = (((bb1 * H_ + hh) * T_ + tt1) << 5) + (dd >> 1);
                uint32_t* dst;
                if (part == 0) {
                    dst = g_q16;
                    const float qs = 0.125f * 1.4426950408889634f;
                    v00 *= qs; v01 *= qs; v10 *= qs; v11 *= qs;
                } else dst = (part == 1) ? g_k16 : g_v16;
                dst[w0] = f2h2(v00, v01);
                dst[w1] = f2h2(v10, v11);
            } else {
                *(float2*)&out[(size_t)r0 * N + n0]       = make_float2(v00, v01);
                *(float2*)&out[(size_t)(r0 + 8) * N + n0] = make_float2(v10, v11);
            }
        }
    }
}

// ---------------------------------------------------------------------------
// FP16 tensor-core causal flash attention (R14 structure).
// V transposition done IN-REGISTER via ldmatrix.trans on natural-layout V:
// no vtrans kernel, no g_vt plane. K and V smem tiles have identical layout
// (rows = key/time, 64 halfs of d + pad = 36 words). No running max;
// per-warp masked-ktile skip. 55.3 KB smem -> 2 CTAs/SM.
// ---------------------------------------------------------------------------
#define BQ 128
#define PW36 36
#define KPW (64*PW36)           // 2304 words per plane
#define BUFW (2*KPW)            // 4608 words per buffer (K + V)
#define PS_OFF (2*BUFW)         // 9216
#define ATTN_SMEM_BYTES ((PS_OFF + BQ*PW36)*4)   // 55296 B

__global__ __launch_bounds__(256, 2)
void attn_mma()
{
    extern __shared__ uint32_t sw[];
    uint32_t sbase;
    asm("{ .reg .u64 t; cvta.to.shared.u64 t, %1; cvt.u32.u64 %0, t; }"
        : "=r"(sbase) : "l"(sw));

    const int tid = threadIdx.x, wid = tid >> 5, lane = tid & 31;
    const int g = lane >> 2, tig = lane & 3;
    const int rowin = lane & 7, mA = lane >> 3;
    const int qt = gridDim.x - 1 - blockIdx.x;   // big tiles first
    const int h = blockIdx.y, b = blockIdx.z;
    const int qbase = qt * BQ;
    const size_t pb2 = (size_t)((b * H_ + h) * T_) * 32;   // q/k/v word base

    // per-lane ldmatrix offsets into a [row][36-word] tile:
    //  - K (non-trans B-frag): rows = key + (mA&1)*8, cols += (mA&2)*16B
    //  - V (trans B-frag): rows = kk + (mA&1)*8, d-cols += (mA&2)*16B  (same!)
    const uint32_t kOff = (uint32_t)(((rowin + ((mA & 1) ? 8 : 0)) * PW36
                                     + ((mA & 2) ? 4 : 0)) * 4);
    const uint32_t pBase = sbase + (uint32_t)(PS_OFF * 4)
        + (uint32_t)(((wid * 16 + rowin + ((mA & 1) ? 8 : 0)) * PW36
                     + ((mA & 2) ? 4 : 0)) * 4);

    // Q fragments (4 k16 steps), register-resident
    uint32_t aq[4][4];
    {
        const uint32_t* q2 = g_q16 + pb2;
        const int r0 = qbase + wid * 16 + g;
        #pragma unroll
        for (int ks = 0; ks < 4; ++ks) {
            aq[ks][0] = q2[(size_t)r0 * 32 + ks * 8 + tig];
            aq[ks][1] = q2[(size_t)(r0 + 8) * 32 + ks * 8 + tig];
            aq[ks][2] = q2[(size_t)r0 * 32 + ks * 8 + tig + 4];
            aq[ks][3] = q2[(size_t)(r0 + 8) * 32 + ks * 8 + tig + 4];
        }
    }

    float oacc[8][4];
    #pragma unroll
    for (int nf = 0; nf < 8; ++nf)
        #pragma unroll
        for (int j = 0; j < 4; ++j) oacc[nf][j] = 0.f;
    float l0 = 0.f, l1 = 0.f;

    const int nkt = 2 * qt + 2;
    const int wmaxrow = qbase + wid * 16 + 15;

    auto ISSUE = [&](int kt, int buf) {
        const uint32_t bufo = buf * BUFW;
        #pragma unroll
        for (int p = 0; p < 2; ++p) {           // K then V, identical layout
            const uint32_t* plane = (p == 0) ? g_k16 : g_v16;
            const uint32_t pofs = bufo + p * KPW;
            #pragma unroll
            for (int i = 0; i < 2; ++i) {
                const int idx = tid + i * 256;
                const int row = idx >> 3, c16 = idx & 7;
                const uint32_t* src = plane + pb2 + (size_t)(kt * 64 + row) * 32 + c16 * 4;
                const uint32_t dst = sbase + (pofs + row * PW36 + c16 * 4) * 4;
                asm volatile("cp.async.cg.shared.global [%0], [%1], 16;"
                             :: "r"(dst), "l"(src) : "memory");
            }
        }
        asm volatile("cp.async.commit_group;" ::: "memory");
    };

    ISSUE(0, 0);
    if (nkt > 1) ISSUE(1, 1);

    for (int kt = 0; kt < nkt; ++kt) {
        if (kt < nkt - 1) asm volatile("cp.async.wait_group 1;" ::: "memory");
        else              asm volatile("cp.async.wait_group 0;" ::: "memory");
        __syncthreads();

        const int ktb = kt * 64;
        if (ktb <= wmaxrow) {   // warp-uniform skip of fully-masked ktiles
            const uint32_t kAddr = sbase + (uint32_t)(((kt & 1) * BUFW) * 4) + kOff;
            const uint32_t vAddr = kAddr + (uint32_t)(KPW * 4);
            uint32_t* Ps = sw + PS_OFF;

            // ---- S = Q K^T (log2 domain) ----
            float sa[8][4];
            #pragma unroll
            for (int nf = 0; nf < 8; ++nf)
                #pragma unroll
                for (int j = 0; j < 4; ++j) sa[nf][j] = 0.f;
            #pragma unroll
            for (int ks = 0; ks < 4; ++ks) {
                #pragma unroll
                for (int j = 0; j < 4; ++j) {
                    uint32_t b0, b1, b2, b3;
                    ldsm4(b0, b1, b2, b3,
                          kAddr + (uint32_t)((j * 16 * PW36 + ks * 8) * 4));
                    mma_f16(sa[2*j],   aq[ks][0], aq[ks][1], aq[ks][2], aq[ks][3], b0, b2);
                    mma_f16(sa[2*j+1], aq[ks][0], aq[ks][1], aq[ks][2], aq[ks][3], b1, b3);
                }
            }

            // ---- causal mask ----
            const int rg0 = qbase + wid * 16 + g, rg1 = rg0 + 8;
            if (ktb + 63 > rg0) {
                #pragma unroll
                for (int nf = 0; nf < 8; ++nf) {
                    const int c0 = ktb + nf * 8 + 2 * tig;
                    if (c0     > rg0) sa[nf][0] = -CUDART_INF_F;
                    if (c0 + 1 > rg0) sa[nf][1] = -CUDART_INF_F;
                    if (c0     > rg1) sa[nf][2] = -CUDART_INF_F;
                    if (c0 + 1 > rg1) sa[nf][3] = -CUDART_INF_F;
                }
            }

            // ---- p = ex2(s); store P (fp16) ----
            float ls0 = 0.f, ls1 = 0.f;
            const int prow = wid * 16 + g;
            #pragma unroll
            for (int nf = 0; nf < 8; ++nf) {
                const float p0 = ex2f(sa[nf][0]), p1 = ex2f(sa[nf][1]);
                const float p2 = ex2f(sa[nf][2]), p3 = ex2f(sa[nf][3]);
                ls0 += p0 + p1; ls1 += p2 + p3;
                Ps[prow * PW36 + nf * 4 + tig]       = f2h2(p0, p1);
                Ps[(prow + 8) * PW36 + nf * 4 + tig] = f2h2(p2, p3);
            }
            l0 += ls0;
            l1 += ls1;
            __syncwarp();   // P rows warp-private

            // ---- O += P V: V^T B-frags via ldmatrix.trans on natural V ----
            #pragma unroll
            for (int ks = 0; ks < 4; ++ks) {
                uint32_t p0, p1, p2, p3;
                ldsm4(p0, p1, p2, p3, pBase + (uint32_t)((ks * 8) * 4));
                #pragma unroll
                for (int j = 0; j < 4; ++j) {
                    uint32_t v0, v1, v2, v3;
                    // rows = kk (ks*16), cols = d (j*16 halfs = j*8 words)
                    ldsm4t(v0, v1, v2, v3,
                           vAddr + (uint32_t)((ks * 16 * PW36 + j * 8) * 4));
                    mma_f16(oacc[2*j],   p0, p1, p2, p3, v0, v1);
                    mma_f16(oacc[2*j+1], p0, p1, p2, p3, v2, v3);
                }
            }
        }

        __syncthreads();
        if (kt + 2 < nkt) ISSUE(kt + 2, kt & 1);
    }

    // ---- row-sum quad reduce + finalize (y fp16 for proj GEMM) ----
    l0 += __shfl_xor_sync(0xffffffffu, l0, 1);
    l0 += __shfl_xor_sync(0xffffffffu, l0, 2);
    l1 += __shfl_xor_sync(0xffffffffu, l1, 1);
    l1 += __shfl_xor_sync(0xffffffffu, l1, 2);
    const float i0 = __frcp_rn(l0), i1 = __frcp_rn(l1);
    const int rg0 = qbase + wid * 16 + g;
    uint32_t* y0 = g_y16 + ((size_t)(b * T_ + rg0) * C_ + h * D_) / 2;
    uint32_t* y1 = g_y16 + ((size_t)(b * T_ + rg0 + 8) * C_ + h * D_) / 2;
    #pragma unroll
    for (int nf = 0; nf < 8; ++nf) {
        y0[nf * 4 + tig] = f2h2(oacc[nf][0] * i0, oacc[nf][1] * i0);
        y1[nf * 4 + tig] = f2h2(oacc[nf][2] * i1, oacc[nf][3] * i1);
    }
}

// ---------------------------------------------------------------------------
extern "C" void kernel_launch(void* const* d_in, const int* in_sizes, int n_in,
                              void* d_out, int out_size)
{
    const float* x      = (const float*)d_in[0];
    const float* w_attn = (const float*)d_in[1];
    const float* b_attn = (const float*)d_in[2];
    const float* w_proj = (const float*)d_in[3];
    const float* b_proj = (const float*)d_in[4];
    float* out = (float*)d_out;

    cudaFuncSetAttribute(gemm_mma<0>, cudaFuncAttributeMaxDynamicSharedMemorySize, GEMM_SMEM);
    cudaFuncSetAttribute(gemm_mma<1>, cudaFuncAttributeMaxDynamicSharedMemorySize, GEMM_SMEM);
    cudaFuncSetAttribute(attn_mma, cudaFuncAttributeMaxDynamicSharedMemorySize, ATTN_SMEM_BYTES);

    uint32_t* px;  cudaGetSymbolAddress((void**)&px,  g_x16);
    uint32_t* pat; cudaGetSymbolAddress((void**)&pat, g_wat16);
    uint32_t* ppt; cudaGetSymbolAddress((void**)&ppt, g_wpt16);
    uint32_t* py;  cudaGetSymbolAddress((void**)&py,  g_y16);

    // 0) convert x to fp16; convert+transpose weights to [N][K] fp16
    conv_f16<<<(S_*C_/4 + 255)/256, 256>>>(x, px, S_*C_/4);
    convT_f16<<<dim3(3*C_/32, C_/64), 256>>>(w_attn, pat, C_, 3*C_);
    convT_f16<<<dim3(C_/32,   C_/64), 256>>>(w_proj, ppt, C_, C_);

    // 1) QKV GEMM (fp16 m16n8k16) -> q/k/v fp16 planes (all natural layout)
    gemm_mma<0><<<dim3(3*C_/128, S_/128), 256, GEMM_SMEM>>>(px, pat, b_attn, nullptr, 3*C_, C_);

    // 2) FP16 tensor-core causal flash attention -> g_y16
    attn_mma<<<dim3(T_/BQ, H_, B_), 256, ATTN_SMEM_BYTES>>>();

    // 3) Proj GEMM (fp16) + bias -> fp32 out
    gemm_mma<1><<<dim3(C_/128, S_/128), 256, GEMM_SMEM>>>(py, ppt, b_proj, out, C_, C_);
}

// round 17
// speedup vs baseline: 1.0737x; 1.0162x over previous
#include <cuda_runtime.h>
#include <cuda_fp16.h>
#include <math_constants.h>
#include <cstdint>

#define B_ 4
#define T_ 2048
#define C_ 1024
#define H_ 16
#define D_ 64
#define S_ (B_*T_)   // 8192

// Scratch (device globals) — all fp16 payloads stored as packed half2 words.
__device__ uint32_t g_x16 [S_*C_/2];        // x as fp16
__device__ uint32_t g_wat16[3*C_*C_/2];     // w_attn TRANSPOSED [N][K] fp16
__device__ uint32_t g_wpt16[C_*C_/2];       // w_proj TRANSPOSED [N][K] fp16
__device__ uint32_t g_y16 [S_*C_/2];        // attention output fp16
__device__ uint32_t g_q16 [B_*H_*T_*D_/2];  // q * (1/8)*log2e, [B,H,T,D]
__device__ uint32_t g_k16 [B_*H_*T_*D_/2];  // [B,H,T,D]
__device__ uint32_t g_v16 [B_*H_*T_*D_/2];  // v natural [B,H,T,D]

// pack two floats -> half2 word {lo, hi}
__device__ __forceinline__ uint32_t f2h2(float lo, float hi) {
    uint32_t r;
    asm("cvt.rn.f16x2.f32 %0, %1, %2;" : "=r"(r) : "f"(hi), "f"(lo));
    return r;
}
// packed half2 2^x (MUFU, one instr per pair; -inf -> +0)
__device__ __forceinline__ uint32_t ex2h2(uint32_t x) {
    uint32_t r;
    asm("ex2.approx.f16x2 %0, %1;" : "=r"(r) : "r"(x));
    return r;
}

// mma.sync m16n8k16 fp16 in / fp32 acc.
__device__ __forceinline__ void mma_f16(float c[4],
                                        uint32_t a0, uint32_t a1, uint32_t a2, uint32_t a3,
                                        uint32_t b0, uint32_t b1) {
    asm volatile(
        "mma.sync.aligned.m16n8k16.row.col.f32.f16.f16.f32 "
        "{%0,%1,%2,%3}, {%4,%5,%6,%7}, {%8,%9}, {%0,%1,%2,%3};"
        : "+f"(c[0]), "+f"(c[1]), "+f"(c[2]), "+f"(c[3])
        : "r"(a0), "r"(a1), "r"(a2), "r"(a3), "r"(b0), "r"(b1));
}

// ldmatrix x4 b16 (non-transposed)
__device__ __forceinline__ void ldsm4(uint32_t& r0, uint32_t& r1,
                                      uint32_t& r2, uint32_t& r3, uint32_t a) {
    asm volatile("ldmatrix.sync.aligned.m8n8.x4.shared.b16 {%0,%1,%2,%3}, [%4];"
                 : "=r"(r0), "=r"(r1), "=r"(r2), "=r"(r3) : "r"(a));
}
// ldmatrix x4 b16 TRANSPOSED
__device__ __forceinline__ void ldsm4t(uint32_t& r0, uint32_t& r1,
                                       uint32_t& r2, uint32_t& r3, uint32_t a) {
    asm volatile("ldmatrix.sync.aligned.m8n8.x4.trans.shared.b16 {%0,%1,%2,%3}, [%4];"
                 : "=r"(r0), "=r"(r1), "=r"(r2), "=r"(r3) : "r"(a));
}

// ---------------------------------------------------------------------------
// fp32 -> fp16 bulk converter (for x)
// ---------------------------------------------------------------------------
__global__ __launch_bounds__(256)
void conv_f16(const float* __restrict__ s, uint32_t* __restrict__ d, int n4)
{
    const int i = blockIdx.x * blockDim.x + threadIdx.x;
    if (i < n4) {
        float4 v = ((const float4*)s)[i];
        ((uint2*)d)[i] = make_uint2(f2h2(v.x, v.y), f2h2(v.z, v.w));
    }
}

// ---------------------------------------------------------------------------
// fp32 [K][N] -> fp16 transposed [N][K]. Tiles of 64 k x 32 n.
// ---------------------------------------------------------------------------
__global__ __launch_bounds__(256)
void convT_f16(const float* __restrict__ w, uint32_t* __restrict__ wt,
               int Kd, int Nd)
{
    __shared__ float t[64][33];
    const int n0 = blockIdx.x * 32, k0 = blockIdx.y * 64;
    const int tid = threadIdx.x;
    #pragma unroll
    for (int i = 0; i < 8; ++i) {
        const int idx = tid + i * 256;
        const int r = idx >> 5, c = idx & 31;
        t[r][c] = w[(size_t)(k0 + r) * Nd + n0 + c];
    }
    __syncthreads();
    #pragma unroll
    for (int i = 0; i < 4; ++i) {
        const int idx = tid + i * 256;
        const int n = idx >> 5, k2 = idx & 31;
        wt[(size_t)(n0 + n) * (Kd / 2) + k0 / 2 + k2] =
            f2h2(t[2 * k2][n], t[2 * k2 + 1][n]);
    }
}

// ---------------------------------------------------------------------------
// FP16 tensor-core GEMM: 128x128 CTA, 256 thr, 2 CTAs/SM, cp.async 3-stage,
// K-chunks of 64 (proven R14/R16 config).
// ---------------------------------------------------------------------------
#define PAW 36
#define AW (128*PAW)         // 4608 words per tile
#define STW (2*AW)           // 9216 words per stage
#define GEMM_SMEM (3*STW*4)  // 110592 B

template<int MODE>
__global__ __launch_bounds__(256, 2)
void gemm_mma(const uint32_t* __restrict__ A2,    // [M][K/2] half2 words
              const uint32_t* __restrict__ Wt2,   // [N][K/2]
              const float* __restrict__ bias,
              float* __restrict__ out,
              int N, int K)
{
    extern __shared__ uint32_t sm4[];
    uint32_t sbase;
    asm("{ .reg .u64 t; cvta.to.shared.u64 t, %1; cvt.u32.u64 %0, t; }"
        : "=r"(sbase) : "l"(sm4));

    const int tid = threadIdx.x;
    const int wid = tid >> 5, lane = tid & 31;
    const int g = lane >> 2, tig = lane & 3;
    const int rowin = lane & 7, mA = lane >> 3;
    const int wm = (wid & 1) * 64;
    const int wn = (wid >> 1) * 32;
    const int bm = blockIdx.y * 128, bn = blockIdx.x * 128;
    const int K2 = K / 2;

    const uint32_t aBase = sbase + (uint32_t)(((wm + rowin + ((mA & 1) ? 8 : 0)) * PAW
                                              + ((mA & 2) ? 4 : 0)) * 4);
    const uint32_t bBase = sbase + (uint32_t)((AW + (wn + rowin + ((mA & 1) ? 8 : 0)) * PAW
                                              + ((mA & 2) ? 4 : 0)) * 4);

    float acc[4][4][4];
    #pragma unroll
    for (int i = 0; i < 4; ++i)
        #pragma unroll
        for (int j = 0; j < 4; ++j)
            #pragma unroll
            for (int k = 0; k < 4; ++k) acc[i][j][k] = 0.f;

    const int nch = K / 64;

    auto ISSUE = [&](int c, int st) {
        const int k0w = c * 32;
        const uint32_t so = st * STW;
        #pragma unroll
        for (int i = 0; i < 4; ++i) {
            const int idx = tid + i * 256;
            const int row = idx >> 3, kq = idx & 7;
            const uint32_t* src = A2 + (size_t)(bm + row) * K2 + k0w + kq * 4;
            const uint32_t dst = sbase + (so + row * PAW + kq * 4) * 4;
            asm volatile("cp.async.cg.shared.global [%0], [%1], 16;"
                         :: "r"(dst), "l"(src) : "memory");
        }
        #pragma unroll
        for (int i = 0; i < 4; ++i) {
            const int idx = tid + i * 256;
            const int row = idx >> 3, kq = idx & 7;
            const uint32_t* src = Wt2 + (size_t)(bn + row) * K2 + k0w + kq * 4;
            const uint32_t dst = sbase + (so + AW + row * PAW + kq * 4) * 4;
            asm volatile("cp.async.cg.shared.global [%0], [%1], 16;"
                         :: "r"(dst), "l"(src) : "memory");
        }
        asm volatile("cp.async.commit_group;" ::: "memory");
    };

    auto COMPUTE = [&](int st) {
        const uint32_t so4 = (uint32_t)(st * STW * 4);
        #pragma unroll
        for (int ks = 0; ks < 4; ++ks) {
            uint32_t af[4][4];
            #pragma unroll
            for (int mf = 0; mf < 4; ++mf)
                ldsm4(af[mf][0], af[mf][1], af[mf][2], af[mf][3],
                      aBase + so4 + (uint32_t)((mf * 16 * PAW + ks * 8) * 4));
            uint32_t bf[4][2];
            #pragma unroll
            for (int j = 0; j < 2; ++j)
                ldsm4(bf[2*j][0], bf[2*j+1][0], bf[2*j][1], bf[2*j+1][1],
                      bBase + so4 + (uint32_t)((j * 16 * PAW + ks * 8) * 4));
            #pragma unroll
            for (int mf = 0; mf < 4; ++mf)
                #pragma unroll
                for (int nf = 0; nf < 4; ++nf)
                    mma_f16(acc[mf][nf], af[mf][0], af[mf][1], af[mf][2], af[mf][3],
                            bf[nf][0], bf[nf][1]);
        }
    };

    ISSUE(0, 0);
    ISSUE(1, 1);
    for (int c = 0; c < nch; ++c) {
        if (c + 1 < nch) asm volatile("cp.async.wait_group 1;" ::: "memory");
        else             asm volatile("cp.async.wait_group 0;" ::: "memory");
        __syncthreads();
        COMPUTE(c % 3);
        if (c + 2 < nch) ISSUE(c + 2, (c + 2) % 3);
    }

    #pragma unroll
    for (int mf = 0; mf < 4; ++mf) {
        const int r0 = bm + wm + mf * 16 + g;
        #pragma unroll
        for (int nf = 0; nf < 4; ++nf) {
            const int n0 = bn + wn + nf * 8 + tig * 2;
            const float bv0 = bias[n0], bv1 = bias[n0 + 1];
            float v00 = acc[mf][nf][0] + bv0, v01 = acc[mf][nf][1] + bv1;
            float v10 = acc[mf][nf][2] + bv0, v11 = acc[mf][nf][3] + bv1;
            if (MODE == 0) {
                const int part = n0 >> 10;
                const int cl = n0 & 1023;
                const int hh = cl >> 6, dd = cl & 63;
                const int bb0 = r0 >> 11, tt0 = r0 & 2047;
                const int r1 = r0 + 8;
                const int bb1 = r1 >> 11, tt1 = r1 & 2047;
                const int w0 = (((bb0 * H_ + hh) * T_ + tt0) << 5) + (dd >> 1);
                const int w1 = (((bb1 * H_ + hh) * T_ + tt1) << 5) + (dd >> 1);
                uint32_t* dst;
                if (part == 0) {
                    dst = g_q16;
                    const float qs = 0.125f * 1.4426950408889634f;
                    v00 *= qs; v01 *= qs; v10 *= qs; v11 *= qs;
                } else dst = (part == 1) ? g_k16 : g_v16;
                dst[w0] = f2h2(v00, v01);
                dst[w1] = f2h2(v10, v11);
            } else {
                *(float2*)&out[(size_t)r0 * N + n0]       = make_float2(v00, v01);
                *(float2*)&out[(size_t)(r0 + 8) * N + n0] = make_float2(v10, v11);
            }
        }
    }
}

// ---------------------------------------------------------------------------
// FP16 tensor-core causal flash attention.
// ex2 done in PACKED HALF2 (halves MUFU work + deletes P-pack cvt);
// row-sums accumulated on the TENSOR pipe via an extra P*ones mma per ks
// (P fragments already in registers -> zero extra loads; no shfl reduce).
// V^T fragments via ldmatrix.trans on natural V. No running max;
// per-warp masked-ktile skip. 55.3 KB smem -> 2 CTAs/SM.
// ---------------------------------------------------------------------------
#define BQ 128
#define PW36 36
#define KPW (64*PW36)           // 2304 words per plane
#define BUFW (2*KPW)            // 4608 words per buffer (K + V)
#define PS_OFF (2*BUFW)         // 9216
#define ATTN_SMEM_BYTES ((PS_OFF + BQ*PW36)*4)   // 55296 B
#define ONES_H2 0x3C003C00u     // half2 {1.0, 1.0}

__global__ __launch_bounds__(256, 2)
void attn_mma()
{
    extern __shared__ uint32_t sw[];
    uint32_t sbase;
    asm("{ .reg .u64 t; cvta.to.shared.u64 t, %1; cvt.u32.u64 %0, t; }"
        : "=r"(sbase) : "l"(sw));

    const int tid = threadIdx.x, wid = tid >> 5, lane = tid & 31;
    const int g = lane >> 2, tig = lane & 3;
    const int rowin = lane & 7, mA = lane >> 3;
    const int qt = gridDim.x - 1 - blockIdx.x;   // big tiles first
    const int h = blockIdx.y, b = blockIdx.z;
    const int qbase = qt * BQ;
    const size_t pb2 = (size_t)((b * H_ + h) * T_) * 32;   // q/k/v word base

    const uint32_t kOff = (uint32_t)(((rowin + ((mA & 1) ? 8 : 0)) * PW36
                                     + ((mA & 2) ? 4 : 0)) * 4);
    const uint32_t pBase = sbase + (uint32_t)(PS_OFF * 4)
        + (uint32_t)(((wid * 16 + rowin + ((mA & 1) ? 8 : 0)) * PW36
                     + ((mA & 2) ? 4 : 0)) * 4);

    // Q fragments (4 k16 steps), register-resident
    uint32_t aq[4][4];
    {
        const uint32_t* q2 = g_q16 + pb2;
        const int r0 = qbase + wid * 16 + g;
        #pragma unroll
        for (int ks = 0; ks < 4; ++ks) {
            aq[ks][0] = q2[(size_t)r0 * 32 + ks * 8 + tig];
            aq[ks][1] = q2[(size_t)(r0 + 8) * 32 + ks * 8 + tig];
            aq[ks][2] = q2[(size_t)r0 * 32 + ks * 8 + tig + 4];
            aq[ks][3] = q2[(size_t)(r0 + 8) * 32 + ks * 8 + tig + 4];
        }
    }

    float oacc[8][4];
    #pragma unroll
    for (int nf = 0; nf < 8; ++nf)
        #pragma unroll
        for (int j = 0; j < 4; ++j) oacc[nf][j] = 0.f;
    float lacc[4] = {0.f, 0.f, 0.f, 0.f};   // row sums via P*ones mma

    const int nkt = 2 * qt + 2;
    const int wmaxrow = qbase + wid * 16 + 15;

    auto ISSUE = [&](int kt, int buf) {
        const uint32_t bufo = buf * BUFW;
        #pragma unroll
        for (int p = 0; p < 2; ++p) {           // K then V, identical layout
            const uint32_t* plane = (p == 0) ? g_k16 : g_v16;
            const uint32_t pofs = bufo + p * KPW;
            #pragma unroll
            for (int i = 0; i < 2; ++i) {
                const int idx = tid + i * 256;
                const int row = idx >> 3, c16 = idx & 7;
                const uint32_t* src = plane + pb2 + (size_t)(kt * 64 + row) * 32 + c16 * 4;
                const uint32_t dst = sbase + (pofs + row * PW36 + c16 * 4) * 4;
                asm volatile("cp.async.cg.shared.global [%0], [%1], 16;"
                             :: "r"(dst), "l"(src) : "memory");
            }
        }
        asm volatile("cp.async.commit_group;" ::: "memory");
    };

    ISSUE(0, 0);
    if (nkt > 1) ISSUE(1, 1);

    for (int kt = 0; kt < nkt; ++kt) {
        if (kt < nkt - 1) asm volatile("cp.async.wait_group 1;" ::: "memory");
        else              asm volatile("cp.async.wait_group 0;" ::: "memory");
        __syncthreads();

        const int ktb = kt * 64;
        if (ktb <= wmaxrow) {   // warp-uniform skip of fully-masked ktiles
            const uint32_t kAddr = sbase + (uint32_t)(((kt & 1) * BUFW) * 4) + kOff;
            const uint32_t vAddr = kAddr + (uint32_t)(KPW * 4);
            uint32_t* Ps = sw + PS_OFF;

            // ---- S = Q K^T (log2 domain) ----
            float sa[8][4];
            #pragma unroll
            for (int nf = 0; nf < 8; ++nf)
                #pragma unroll
                for (int j = 0; j < 4; ++j) sa[nf][j] = 0.f;
            #pragma unroll
            for (int ks = 0; ks < 4; ++ks) {
                #pragma unroll
                for (int j = 0; j < 4; ++j) {
                    uint32_t b0, b1, b2, b3;
                    ldsm4(b0, b1, b2, b3,
                          kAddr + (uint32_t)((j * 16 * PW36 + ks * 8) * 4));
                    mma_f16(sa[2*j],   aq[ks][0], aq[ks][1], aq[ks][2], aq[ks][3], b0, b2);
                    mma_f16(sa[2*j+1], aq[ks][0], aq[ks][1], aq[ks][2], aq[ks][3], b1, b3);
                }
            }

            // ---- causal mask ----
            const int rg0 = qbase + wid * 16 + g, rg1 = rg0 + 8;
            if (ktb + 63 > rg0) {
                #pragma unroll
                for (int nf = 0; nf < 8; ++nf) {
                    const int c0 = ktb + nf * 8 + 2 * tig;
                    if (c0     > rg0) sa[nf][0] = -CUDART_INF_F;
                    if (c0 + 1 > rg0) sa[nf][1] = -CUDART_INF_F;
                    if (c0     > rg1) sa[nf][2] = -CUDART_INF_F;
                    if (c0 + 1 > rg1) sa[nf][3] = -CUDART_INF_F;
                }
            }

            // ---- p = ex2(s) in packed half2; store P directly ----
            const int prow = wid * 16 + g;
            #pragma unroll
            for (int nf = 0; nf < 8; ++nf) {
                const uint32_t ph01 = ex2h2(f2h2(sa[nf][0], sa[nf][1]));
                const uint32_t ph23 = ex2h2(f2h2(sa[nf][2], sa[nf][3]));
                Ps[prow * PW36 + nf * 4 + tig]       = ph01;
                Ps[(prow + 8) * PW36 + nf * 4 + tig] = ph23;
            }
            __syncwarp();   // P rows warp-private

            // ---- O += P V; row-sum l += P * ones (tensor pipe) ----
            #pragma unroll
            for (int ks = 0; ks < 4; ++ks) {
                uint32_t p0, p1, p2, p3;
                ldsm4(p0, p1, p2, p3, pBase + (uint32_t)((ks * 8) * 4));
                mma_f16(lacc, p0, p1, p2, p3, ONES_H2, ONES_H2);
                #pragma unroll
                for (int j = 0; j < 4; ++j) {
                    uint32_t v0, v1, v2, v3;
                    ldsm4t(v0, v1, v2, v3,
                           vAddr + (uint32_t)((ks * 16 * PW36 + j * 8) * 4));
                    mma_f16(oacc[2*j],   p0, p1, p2, p3, v0, v1);
                    mma_f16(oacc[2*j+1], p0, p1, p2, p3, v2, v3);
                }
            }
        }

        __syncthreads();
        if (kt + 2 < nkt) ISSUE(kt + 2, kt & 1);
    }

    // ---- finalize: l in lacc[0]/lacc[2] (every column = row sum) ----
    const float i0 = __frcp_rn(lacc[0]), i1 = __frcp_rn(lacc[2]);
    const int rg0 = qbase + wid * 16 + g;
    uint32_t* y0 = g_y16 + ((size_t)(b * T_ + rg0) * C_ + h * D_) / 2;
    uint32_t* y1 = g_y16 + ((size_t)(b * T_ + rg0 + 8) * C_ + h * D_) / 2;
    #pragma unroll
    for (int nf = 0; nf < 8; ++nf) {
        y0[nf * 4 + tig] = f2h2(oacc[nf][0] * i0, oacc[nf][1] * i0);
        y1[nf * 4 + tig] = f2h2(oacc[nf][2] * i1, oacc[nf][3] * i1);
    }
}

// ---------------------------------------------------------------------------
extern "C" void kernel_launch(void* const* d_in, const int* in_sizes, int n_in,
                              void* d_out, int out_size)
{
    const float* x      = (const float*)d_in[0];
    const float* w_attn = (const float*)d_in[1];
    const float* b_attn = (const float*)d_in[2];
    const float* w_proj = (const float*)d_in[3];
    const float* b_proj = (const float*)d_in[4];
    float* out = (float*)d_out;

    cudaFuncSetAttribute(gemm_mma<0>, cudaFuncAttributeMaxDynamicSharedMemorySize, GEMM_SMEM);
    cudaFuncSetAttribute(gemm_mma<1>, cudaFuncAttributeMaxDynamicSharedMemorySize, GEMM_SMEM);
    cudaFuncSetAttribute(attn_mma, cudaFuncAttributeMaxDynamicSharedMemorySize, ATTN_SMEM_BYTES);

    uint32_t* px;  cudaGetSymbolAddress((void**)&px,  g_x16);
    uint32_t* pat; cudaGetSymbolAddress((void**)&pat, g_wat16);
    uint32_t* ppt; cudaGetSymbolAddress((void**)&ppt, g_wpt16);
    uint32_t* py;  cudaGetSymbolAddress((void**)&py,  g_y16);

    // 0) convert x to fp16; convert+transpose weights to [N][K] fp16
    conv_f16<<<(S_*C_/4 + 255)/256, 256>>>(x, px, S_*C_/4);
    convT_f16<<<dim3(3*C_/32, C_/64), 256>>>(w_attn, pat, C_, 3*C_);
    convT_f16<<<dim3(C_/32,   C_/64), 256>>>(w_proj, ppt, C_, C_);

    // 1) QKV GEMM (fp16 m16n8k16) -> q/k/v fp16 planes (natural layout)
    gemm_mma<0><<<dim3(3*C_/128, S_/128), 256, GEMM_SMEM>>>(px, pat, b_attn, nullptr, 3*C_, C_);

    // 2) FP16 tensor-core causal flash attention -> g_y16
    attn_mma<<<dim3(T_/BQ, H_, B_), 256, ATTN_SMEM_BYTES>>>();

    // 3) Proj GEMM (fp16) + bias -> fp32 out
    gemm_mma<1><<<dim3(C_/128, S_/128), 256, GEMM_SMEM>>>(py, ppt, b_proj, out, C_, C_);
}